// round 14
// baseline (speedup 1.0000x reference)
#include <cuda_runtime.h>
#include <cuda_fp16.h>
#include <cstdint>

#define DIMC   192
#define NH     6
#define HD     32
#define MLEN   256
#define NTOK   16384
#define BATCH  4
#define TILE   128

// softmax scale * log2(e), folded into Wq
#define QSCALE 0.25504157602086453f

// ---- device-global scratch (no runtime allocation allowed) ----
__device__ __half g_k [BATCH * MLEN * DIMC];   // [b][m][c] fp16
__device__ __half g_v [BATCH * MLEN * DIMC];   // [b][m][c] fp16
__device__ __half g_wq[DIMC * DIMC];           // Wq * QSCALE, row-major [k][n]
__device__ __half g_wp[DIMC * DIMC];           // Wp, row-major [k][n]
__device__ unsigned g_flag_w  = 0;             // monotonic: +1 per weight-prep CTA
__device__ unsigned g_flag_kv = 0;             // monotonic: +1 per KV CTA

// ---------------- smem byte offsets (shared by all roles) ----------------
#define O_XQ   0            // X -> Q -> O: fp16 [128] rows, 400B stride (51200)
#define O_KV   51200        // union: W chunk [96]x400B (38400) | K [256]x80B + V [256]x80B
#define O_V    71680        // V = O_KV + 20480
#define O_BP   92160        // bias fp32 [192]
#define SMEM_BYTES (O_BP + 768 + 256)   // 93184  (2 CTAs/SM)

#define NW_BLK   72          // weight-prep CTAs
#define NKV_BLK  32          // KV-projection CTAs
#define NPREP    (NW_BLK + NKV_BLK)

// ========================= helpers =========================
__device__ __forceinline__ uint32_t smem_u32(const void* p) {
    uint32_t a;
    asm("{ .reg .u64 t; cvta.to.shared.u64 t, %1; cvt.u32.u64 %0, t; }" : "=r"(a) : "l"(p));
    return a;
}
__device__ __forceinline__ float ex2f(float x) {
    float r; asm("ex2.approx.f32 %0, %1;" : "=f"(r) : "f"(x)); return r;
}
__device__ __forceinline__ uint32_t ex2_h2(uint32_t x) {
    uint32_t r; asm("ex2.approx.f16x2 %0, %1;" : "=r"(r) : "r"(x)); return r;
}
__device__ __forceinline__ uint32_t pack_h2(float lo, float hi) {
    uint32_t r; asm("cvt.rn.f16x2.f32 %0, %1, %2;" : "=r"(r) : "f"(hi), "f"(lo)); return r;
}
__device__ __forceinline__ void ldsm4(uint32_t r[4], uint32_t addr) {
    asm volatile("ldmatrix.sync.aligned.m8n8.x4.shared.b16 {%0,%1,%2,%3}, [%4];"
                 : "=r"(r[0]), "=r"(r[1]), "=r"(r[2]), "=r"(r[3]) : "r"(addr));
}
__device__ __forceinline__ void ldsm4t(uint32_t r[4], uint32_t addr) {
    asm volatile("ldmatrix.sync.aligned.m8n8.x4.trans.shared.b16 {%0,%1,%2,%3}, [%4];"
                 : "=r"(r[0]), "=r"(r[1]), "=r"(r[2]), "=r"(r[3]) : "r"(addr));
}
__device__ __forceinline__ void mma16816(float c[4], const uint32_t a[4],
                                         uint32_t b0, uint32_t b1) {
    asm volatile("mma.sync.aligned.m16n8k16.row.col.f32.f16.f16.f32 "
                 "{%0,%1,%2,%3},{%4,%5,%6,%7},{%8,%9},{%0,%1,%2,%3};"
                 : "+f"(c[0]), "+f"(c[1]), "+f"(c[2]), "+f"(c[3])
                 : "r"(a[0]), "r"(a[1]), "r"(a[2]), "r"(a[3]), "r"(b0), "r"(b1));
}
#define CP16(dst, src) \
    asm volatile("cp.async.cg.shared.global [%0], [%1], 16;" :: "r"(dst), "l"(src))
#define CP_COMMIT() asm volatile("cp.async.commit_group;" ::: "memory")
#define CP_WAIT0()  asm volatile("cp.async.wait_group 0;" ::: "memory")

__device__ __forceinline__ void spin_until(unsigned* flag, unsigned target) {
    while (atomicAdd(flag, 0u) < target) __nanosleep(64);
}

// =====================================================================
// ONE kernel, three roles by blockIdx.x:
//   [0, 72):    weight prep -> g_wq (scaled), g_wp ; bump g_flag_w
//   [72, 104):  HMMA KV projection -> g_k, g_v    ; bump g_flag_kv
//   [104, 616): fused tile pipeline (waits on flags)
// =====================================================================
__global__ __launch_bounds__(256, 2) void mega_kernel(
    const float* __restrict__ x,
    const float* __restrict__ prior,
    const float* __restrict__ g1, const float* __restrict__ b1,
    const float* __restrict__ g2, const float* __restrict__ b2,
    const float* __restrict__ Wq, const float* __restrict__ Wkv,
    const float* __restrict__ Wp, const float* __restrict__ bp,
    float* __restrict__ out)
{
    extern __shared__ char smraw[];
    const uint32_t SB = smem_u32(smraw);
    int tid  = threadIdx.x;
    int wid  = tid >> 5, lane = tid & 31;
    int gid  = lane >> 2, t4 = lane & 3;
    const uint32_t l15 = lane & 15;
    const uint32_t chalf = (lane >> 4) * 16;

    // ================= role 1: weight prep =================
    if (blockIdx.x < NW_BLK) {
        int base = (int)blockIdx.x * 512 + tid;
        #pragma unroll
        for (int it = 0; it < 2; it++) {
            int idx = base + it*256;
            g_wq[idx] = __float2half_rn(Wq[idx] * QSCALE);
            g_wp[idx] = __float2half_rn(Wp[idx]);
        }
        __threadfence();
        __syncthreads();
        if (tid == 0) atomicAdd(&g_flag_w, 1u);
        return;
    }

    // ================= role 2: KV projection =================
    if (blockIdx.x < NPREP) {
        uint32_t* Au = reinterpret_cast<uint32_t*>(smraw + O_XQ);   // stride 100 u32
        uint32_t* Wu = reinterpret_cast<uint32_t*>(smraw + O_KV);   // stride 100 u32

        int kvb = (int)blockIdx.x - NW_BLK;          // 0..31
        int b   = kvb >> 3;
        int m0  = ((kvb >> 2) & 1) * 128;
        int nq  = kvb & 3;

        // load prior tile fp32 -> fp16
        const float2* psrc = reinterpret_cast<const float2*>(
            prior + (size_t)(b*MLEN + m0) * DIMC);
        for (int idx = tid; idx < 128*96; idx += 256) {
            float2 v = psrc[idx];
            Au[(idx / 96)*100 + (idx % 96)] = pack_h2(v.x, v.y);
        }
        __syncthreads();

        // LN in place
        {
            int row = tid >> 1, hf = tid & 1;
            float s = 0.f, s2 = 0.f;
            uint32_t vals[48];
            #pragma unroll
            for (int j = 0; j < 48; j++) {
                vals[j] = Au[row*100 + hf*48 + j];
                float2 f = __half22float2(*reinterpret_cast<__half2*>(&vals[j]));
                s += f.x + f.y;  s2 += f.x*f.x + f.y*f.y;
            }
            s  += __shfl_xor_sync(0xffffffffu, s, 1);
            s2 += __shfl_xor_sync(0xffffffffu, s2, 1);
            float mu   = s * (1.f/DIMC);
            float rstd = rsqrtf(s2*(1.f/DIMC) - mu*mu + 1e-5f);
            #pragma unroll
            for (int j = 0; j < 48; j++) {
                int k = hf*96 + 2*j;
                float2 f = __half22float2(*reinterpret_cast<__half2*>(&vals[j]));
                float v0 = (f.x - mu) * rstd * __ldg(g2 + k)     + __ldg(b2 + k);
                float v1 = (f.y - mu) * rstd * __ldg(g2 + k + 1) + __ldg(b2 + k + 1);
                Au[row*100 + hf*48 + j] = pack_h2(v0, v1);
            }
        }

        // GEMM [128x192] @ [192x96], two 96-row W chunks
        int mw = wid >> 1, nw = wid & 1;
        float acc[2][6][4];
        #pragma unroll
        for (int mi = 0; mi < 2; mi++)
            #pragma unroll
            for (int j = 0; j < 6; j++)
                #pragma unroll
                for (int q = 0; q < 4; q++) acc[mi][j][q] = 0.f;

        uint32_t xa0 = SB + O_XQ + (mw*32 +      l15)*400 + chalf;
        uint32_t xa1 = SB + O_XQ + (mw*32 + 16 + l15)*400 + chalf;
        uint32_t wa  = SB + O_KV + l15*400 + chalf + nw*96;

        #pragma unroll
        for (int kc = 0; kc < 2; kc++) {
            __syncthreads();   // kc=0: LN done; kc=1: prior W chunk reads done
            for (int idx = tid; idx < 96*48; idx += 256) {
                int r = idx / 48, cp = idx % 48;
                const float2* wsrc = reinterpret_cast<const float2*>(
                    Wkv + (size_t)(kc*96 + r)*384 + nq*96);
                float2 v = wsrc[cp];
                Wu[r*100 + cp] = pack_h2(v.x, v.y);
            }
            __syncthreads();

            #pragma unroll
            for (int ks = 0; ks < 6; ks++) {
                uint32_t a0[4], a1[4];
                ldsm4(a0, xa0 + kc*192 + ks*32);
                ldsm4(a1, xa1 + kc*192 + ks*32);
                #pragma unroll
                for (int j = 0; j < 3; j++) {
                    uint32_t bb[4];
                    ldsm4t(bb, wa + ks*16*400 + j*32);
                    mma16816(acc[0][2*j],   a0, bb[0], bb[1]);
                    mma16816(acc[0][2*j+1], a0, bb[2], bb[3]);
                    mma16816(acc[1][2*j],   a1, bb[0], bb[1]);
                    mma16816(acc[1][2*j+1], a1, bb[2], bb[3]);
                }
            }
        }

        // store fragments to g_k / g_v
        uint32_t* dst = reinterpret_cast<uint32_t*>((nq < 2) ? g_k : g_v);
        int cbase = (nq & 1) * 48;
        #pragma unroll
        for (int mi = 0; mi < 2; mi++) {
            int r = mw*32 + mi*16 + gid;
            size_t row0 = (size_t)(b*MLEN + m0 + r) * 96;
            size_t row8 = row0 + 8*96;
            #pragma unroll
            for (int j = 0; j < 6; j++) {
                int cu = cbase + nw*24 + j*4 + t4;
                dst[row0 + cu] = pack_h2(acc[mi][j][0], acc[mi][j][1]);
                dst[row8 + cu] = pack_h2(acc[mi][j][2], acc[mi][j][3]);
            }
        }
        __threadfence();
        __syncthreads();
        if (tid == 0) atomicAdd(&g_flag_kv, 1u);
        return;
    }

    // ================= role 3: fused tile pipeline =================
    uint32_t* XQu = reinterpret_cast<uint32_t*>(smraw + O_XQ);   // stride 100 u32
    float*    bps = reinterpret_cast<float*>(smraw + O_BP);

    int fbid = (int)blockIdx.x - NPREP;
    int b    = fbid >> 7;
    int n0   = (fbid & 127) * TILE;
    const size_t xbase = (size_t)b * DIMC * NTOK;

    const uint32_t l7  = lane & 7;
    const uint32_t mrow8 = ((lane >> 4) << 3);
    const uint32_t d8  = ((lane >> 3) & 1) * 16;

    auto stage_w = [&](const __half* W, int chunk) {
        const char* src = (const char*)W + chunk*96*384;
        #pragma unroll
        for (int it = 0; it < 9; it++) {
            int idx = tid + it*256;
            int r = idx / 24, ch = (idx % 24) * 16;
            CP16(SB + O_KV + r*400 + ch, src + r*384 + ch);
        }
        CP_COMMIT();
    };
    auto stage_k = [&](int h) {
        const char* ksrc = (const char*)(g_k + (size_t)b*MLEN*DIMC + h*HD);
        #pragma unroll
        for (int it = 0; it < 4; it++) {
            int idx = tid + it*256;
            int m = idx >> 2, ch = (idx & 3) * 16;
            CP16(SB + O_KV + m*80 + ch, ksrc + m*(DIMC*2) + ch);
        }
        CP_COMMIT();
    };
    auto stage_v = [&](int h) {
        const char* vsrc = (const char*)(g_v + (size_t)b*MLEN*DIMC + h*HD);
        #pragma unroll
        for (int it = 0; it < 4; it++) {
            int idx = tid + it*256;
            int m = idx >> 2, ch = (idx & 3) * 16;
            CP16(SB + O_V + m*80 + ch, vsrc + m*(DIMC*2) + ch);
        }
        CP_COMMIT();
    };

    for (int i = tid; i < DIMC; i += 256) bps[i] = bp[i];

    // ---------- phase 1: load x as fp16 into XQ ----------
    for (int idx = tid; idx < TILE*(DIMC/2); idx += 256) {
        int cp = idx >> 7, i = idx & 127;
        float v0 = x[xbase + (size_t)(2*cp  )*NTOK + n0 + i];
        float v1 = x[xbase + (size_t)(2*cp+1)*NTOK + n0 + i];
        XQu[i*100 + cp] = pack_h2(v0, v1);
    }
    if (tid == 0) spin_until(&g_flag_w, NW_BLK);   // weights ready (usually instant)
    __syncthreads();   // x stores + flag visible to all
    __threadfence();
    stage_w(g_wq, 0);  // prefetch Wq chunk 0 under LN

    // LN in place
    {
        int row = tid >> 1, hf = tid & 1;
        float s = 0.f, s2 = 0.f;
        uint32_t vals[48];
        #pragma unroll
        for (int j = 0; j < 48; j++) {
            vals[j] = XQu[row*100 + hf*48 + j];
            float2 f = __half22float2(*reinterpret_cast<__half2*>(&vals[j]));
            s += f.x + f.y;  s2 += f.x*f.x + f.y*f.y;
        }
        s  += __shfl_xor_sync(0xffffffffu, s, 1);
        s2 += __shfl_xor_sync(0xffffffffu, s2, 1);
        float mu   = s * (1.f/DIMC);
        float rstd = rsqrtf(s2*(1.f/DIMC) - mu*mu + 1e-5f);
        #pragma unroll
        for (int j = 0; j < 48; j++) {
            int k = hf*96 + 2*j;
            float2 f = __half22float2(*reinterpret_cast<__half2*>(&vals[j]));
            float v0 = (f.x - mu) * rstd * __ldg(g1 + k)     + __ldg(b1 + k);
            float v1 = (f.y - mu) * rstd * __ldg(g1 + k + 1) + __ldg(b1 + k + 1);
            XQu[row*100 + hf*48 + j] = pack_h2(v0, v1);
        }
    }
    CP_WAIT0();
    __syncthreads();   // LN stores + Wq chunk 0 visible

    int mw = wid >> 1, nw = wid & 1;

    // ---------- phase 2: Qproj  Q = X @ Wq(scaled), 2 K-chunks ----------
    {
        float acc[2][12][4];
        #pragma unroll
        for (int mi = 0; mi < 2; mi++)
            #pragma unroll
            for (int j = 0; j < 12; j++)
                #pragma unroll
                for (int q = 0; q < 4; q++) acc[mi][j][q] = 0.f;

        uint32_t xa0 = SB + O_XQ + (mw*32 +      l15)*400 + chalf;
        uint32_t xa1 = SB + O_XQ + (mw*32 + 16 + l15)*400 + chalf;
        uint32_t wa  = SB + O_KV + l15*400 + chalf + nw*192;

        #pragma unroll
        for (int kc = 0; kc < 2; kc++) {
            #pragma unroll
            for (int ks = 0; ks < 6; ks++) {
                uint32_t a0[4], a1[4];
                ldsm4(a0, xa0 + kc*192 + ks*32);
                ldsm4(a1, xa1 + kc*192 + ks*32);
                #pragma unroll
                for (int j = 0; j < 6; j++) {
                    uint32_t bb[4];
                    ldsm4t(bb, wa + ks*16*400 + j*32);
                    mma16816(acc[0][2*j],   a0, bb[0], bb[1]);
                    mma16816(acc[0][2*j+1], a0, bb[2], bb[3]);
                    mma16816(acc[1][2*j],   a1, bb[0], bb[1]);
                    mma16816(acc[1][2*j+1], a1, bb[2], bb[3]);
                }
            }
            __syncthreads();
            if (kc == 0) {
                stage_w(g_wq, 1);
                CP_WAIT0();
                __syncthreads();
            }
        }

        if (tid == 0) spin_until(&g_flag_kv, NKV_BLK);   // K/V ready
        __syncthreads();
        __threadfence();
        stage_k(0);
        stage_v(0);

        #pragma unroll
        for (int mi = 0; mi < 2; mi++) {
            int r = mw*32 + mi*16 + gid;
            #pragma unroll
            for (int j = 0; j < 12; j++) {
                int cu = nw*48 + j*4 + t4;
                XQu[r*100 + cu]       = pack_h2(acc[mi][j][0], acc[mi][j][1]);
                XQu[(r + 8)*100 + cu] = pack_h2(acc[mi][j][2], acc[mi][j][3]);
            }
        }
    }

    // ---------- phase 3: attention heads (flash-split, f16x2 softmax) ----------
    for (int h = 0; h < NH; h++) {
        CP_WAIT0();
        __syncthreads();   // K/V(h) + (h=0) Q stores visible

        uint32_t qa = SB + O_XQ + (wid*16 + l15)*400 + chalf + h*64;
        uint32_t qf[2][4];
        ldsm4(qf[0], qa);
        ldsm4(qf[1], qa + 32);

        float oc[4][4];
        #pragma unroll
        for (int n = 0; n < 4; n++)
            #pragma unroll
            for (int q = 0; q < 4; q++) oc[n][q] = 0.f;
        float mxl = -1e30f, mxh = -1e30f, sl = 0.f, sh = 0.f;

        #pragma unroll
        for (int half = 0; half < 2; half++) {
            float sa[16][4];
            #pragma unroll
            for (int n = 0; n < 16; n++)
                #pragma unroll
                for (int q = 0; q < 4; q++) sa[n][q] = 0.f;

            uint32_t ka = SB + O_KV + (half*128 + l7 + mrow8)*80 + d8;
            #pragma unroll
            for (int ks = 0; ks < 2; ks++) {
                #pragma unroll
                for (int jm = 0; jm < 8; jm++) {
                    uint32_t bb[4];
                    ldsm4(bb, ka + jm*16*80 + ks*32);
                    mma16816(sa[2*jm],   qf[ks], bb[0], bb[1]);
                    mma16816(sa[2*jm+1], qf[ks], bb[2], bb[3]);
                }
            }

            if (half == 1) {
                __syncthreads();
                if (h + 1 < NH) stage_k(h + 1);
            }

            float cml = -1e30f, cmh = -1e30f;
            #pragma unroll
            for (int n = 0; n < 16; n++) {
                cml = fmaxf(cml, fmaxf(sa[n][0], sa[n][1]));
                cmh = fmaxf(cmh, fmaxf(sa[n][2], sa[n][3]));
            }
            cml = fmaxf(cml, __shfl_xor_sync(0xffffffffu, cml, 1));
            cml = fmaxf(cml, __shfl_xor_sync(0xffffffffu, cml, 2));
            cmh = fmaxf(cmh, __shfl_xor_sync(0xffffffffu, cmh, 1));
            cmh = fmaxf(cmh, __shfl_xor_sync(0xffffffffu, cmh, 2));
            float nml = fmaxf(mxl, cml), nmh = fmaxf(mxh, cmh);
            float fl = ex2f(mxl - nml), fh = ex2f(mxh - nmh);
            mxl = nml; mxh = nmh;

            uint32_t pe[16][2];
            float csl = 0.f, csh = 0.f;
            #pragma unroll
            for (int n = 0; n < 16; n++) {
                pe[n][0] = ex2_h2(pack_h2(sa[n][0] - nml, sa[n][1] - nml));
                pe[n][1] = ex2_h2(pack_h2(sa[n][2] - nmh, sa[n][3] - nmh));
                float2 e0 = __half22float2(*reinterpret_cast<__half2*>(&pe[n][0]));
                float2 e1 = __half22float2(*reinterpret_cast<__half2*>(&pe[n][1]));
                csl += e0.x + e0.y;
                csh += e1.x + e1.y;
            }
            csl += __shfl_xor_sync(0xffffffffu, csl, 1);
            csl += __shfl_xor_sync(0xffffffffu, csl, 2);
            csh += __shfl_xor_sync(0xffffffffu, csh, 1);
            csh += __shfl_xor_sync(0xffffffffu, csh, 2);
            sl = sl*fl + csl;
            sh = sh*fh + csh;
            #pragma unroll
            for (int n = 0; n < 4; n++) {
                oc[n][0] *= fl; oc[n][1] *= fl;
                oc[n][2] *= fh; oc[n][3] *= fh;
            }

            uint32_t va = SB + O_V + (half*128 + l15)*80 + chalf;
            #pragma unroll
            for (int kt = 0; kt < 8; kt++) {
                uint32_t a[4];
                a[0] = pe[2*kt][0];
                a[1] = pe[2*kt][1];
                a[2] = pe[2*kt+1][0];
                a[3] = pe[2*kt+1][1];
                #pragma unroll
                for (int j = 0; j < 2; j++) {
                    uint32_t bb[4];
                    ldsm4t(bb, va + kt*16*80 + j*32);
                    mma16816(oc[2*j],   a, bb[0], bb[1]);
                    mma16816(oc[2*j+1], a, bb[2], bb[3]);
                }
            }
        }

        float il = 1.f / sl, ih = 1.f / sh;
        int rl = wid*16 + gid;
        #pragma unroll
        for (int n = 0; n < 4; n++) {
            XQu[rl*100     + h*16 + n*4 + t4] = pack_h2(oc[n][0]*il, oc[n][1]*il);
            XQu[(rl+8)*100 + h*16 + n*4 + t4] = pack_h2(oc[n][2]*ih, oc[n][3]*ih);
        }
        __syncthreads();   // V reads done before restage
        if (h + 1 < NH) stage_v(h + 1);
        else            stage_w(g_wp, 0);
    }

    // ---------- phase 4: outproj (2 K-chunks) + direct epilogue ----------
    {
        CP_WAIT0();
        __syncthreads();   // Wp chunk 0 + all O stores visible

        float acc[2][12][4];
        #pragma unroll
        for (int mi = 0; mi < 2; mi++)
            #pragma unroll
            for (int j = 0; j < 12; j++)
                #pragma unroll
                for (int q = 0; q < 4; q++) acc[mi][j][q] = 0.f;

        uint32_t xa0 = SB + O_XQ + (mw*32 +      l15)*400 + chalf;
        uint32_t xa1 = SB + O_XQ + (mw*32 + 16 + l15)*400 + chalf;
        uint32_t wa  = SB + O_KV + l15*400 + chalf + nw*192;

        #pragma unroll
        for (int kc = 0; kc < 2; kc++) {
            #pragma unroll
            for (int ks = 0; ks < 6; ks++) {
                uint32_t a0[4], a1[4];
                ldsm4(a0, xa0 + kc*192 + ks*32);
                ldsm4(a1, xa1 + kc*192 + ks*32);
                #pragma unroll
                for (int j = 0; j < 6; j++) {
                    uint32_t bb[4];
                    ldsm4t(bb, wa + ks*16*400 + j*32);
                    mma16816(acc[0][2*j],   a0, bb[0], bb[1]);
                    mma16816(acc[0][2*j+1], a0, bb[2], bb[3]);
                    mma16816(acc[1][2*j],   a1, bb[0], bb[1]);
                    mma16816(acc[1][2*j+1], a1, bb[2], bb[3]);
                }
            }
            if (kc == 0) {
                __syncthreads();
                stage_w(g_wp, 1);
                CP_WAIT0();
                __syncthreads();
            }
        }

        #pragma unroll
        for (int mi = 0; mi < 2; mi++) {
            int r = mw*32 + mi*16 + gid;
            #pragma unroll
            for (int j = 0; j < 12; j++) {
                int c = nw*96 + j*8 + t4*2;
                size_t g0  = xbase + (size_t)c*NTOK + n0 + r;
                size_t g1a = g0 + NTOK;
                out[g0]      = acc[mi][j][0] + bps[c]     + __ldg(x + g0);
                out[g1a]     = acc[mi][j][1] + bps[c + 1] + __ldg(x + g1a);
                out[g0 + 8]  = acc[mi][j][2] + bps[c]     + __ldg(x + g0 + 8);
                out[g1a + 8] = acc[mi][j][3] + bps[c + 1] + __ldg(x + g1a + 8);
            }
        }
    }
}

// =====================================================================
extern "C" void kernel_launch(void* const* d_in, const int* in_sizes, int n_in,
                              void* d_out, int out_size)
{
    (void)in_sizes; (void)n_in; (void)out_size;
    const float* x     = (const float*)d_in[0];
    const float* prior = (const float*)d_in[1];
    const float* ln1_g = (const float*)d_in[2];
    const float* ln1_b = (const float*)d_in[3];
    const float* ln2_g = (const float*)d_in[4];
    const float* ln2_b = (const float*)d_in[5];
    const float* Wq    = (const float*)d_in[6];
    const float* Wkv   = (const float*)d_in[7];
    const float* Wp    = (const float*)d_in[8];
    const float* bp    = (const float*)d_in[9];
    float* out = (float*)d_out;

    cudaFuncSetAttribute(mega_kernel, cudaFuncAttributeMaxDynamicSharedMemorySize, SMEM_BYTES);
    mega_kernel<<<NPREP + BATCH * (NTOK/TILE), 256, SMEM_BYTES>>>(
        x, prior, ln1_g, ln1_b, ln2_g, ln2_b, Wq, Wkv, Wp, bp, out);
}

// round 15
// speedup vs baseline: 1.2020x; 1.2020x over previous
#include <cuda_runtime.h>
#include <cuda_fp16.h>
#include <cstdint>

#define DIMC   192
#define NH     6
#define HD     32
#define MLEN   256
#define NTOK   16384
#define BATCH  4
#define TILE   128

// softmax scale * log2(e), folded into Wq conversion
#define QSCALE 0.25504157602086453f

// ---- device-global scratch (no runtime allocation allowed) ----
__device__ __half g_k [BATCH * MLEN * DIMC];   // [b][m][c] fp16
__device__ __half g_v [BATCH * MLEN * DIMC];   // [b][m][c] fp16
__device__ unsigned g_flag_kv = 0;             // monotonic: +1 per KV CTA

// ---------------- smem byte offsets (both roles) ----------------
#define O_XQ   0            // X -> Q -> O: fp16 [128] rows, 400B stride (51200)
#define O_KV   51200        // union: W chunk [96]x400B (38400) | K [256]x80B + V [256]x80B
#define O_V    71680        // V = O_KV + 20480
#define O_BP   92160        // bias fp32 [192]
#define SMEM_BYTES (O_BP + 768 + 256)   // 93184  (2 CTAs/SM)

#define NKV_BLK  32

// ========================= helpers =========================
__device__ __forceinline__ uint32_t smem_u32(const void* p) {
    uint32_t a;
    asm("{ .reg .u64 t; cvta.to.shared.u64 t, %1; cvt.u32.u64 %0, t; }" : "=r"(a) : "l"(p));
    return a;
}
__device__ __forceinline__ float ex2f(float x) {
    float r; asm("ex2.approx.f32 %0, %1;" : "=f"(r) : "f"(x)); return r;
}
__device__ __forceinline__ uint32_t ex2_h2(uint32_t x) {
    uint32_t r; asm("ex2.approx.f16x2 %0, %1;" : "=r"(r) : "r"(x)); return r;
}
__device__ __forceinline__ uint32_t pack_h2(float lo, float hi) {
    uint32_t r; asm("cvt.rn.f16x2.f32 %0, %1, %2;" : "=r"(r) : "f"(hi), "f"(lo)); return r;
}
__device__ __forceinline__ void ldsm4(uint32_t r[4], uint32_t addr) {
    asm volatile("ldmatrix.sync.aligned.m8n8.x4.shared.b16 {%0,%1,%2,%3}, [%4];"
                 : "=r"(r[0]), "=r"(r[1]), "=r"(r[2]), "=r"(r[3]) : "r"(addr));
}
__device__ __forceinline__ void ldsm4t(uint32_t r[4], uint32_t addr) {
    asm volatile("ldmatrix.sync.aligned.m8n8.x4.trans.shared.b16 {%0,%1,%2,%3}, [%4];"
                 : "=r"(r[0]), "=r"(r[1]), "=r"(r[2]), "=r"(r[3]) : "r"(addr));
}
__device__ __forceinline__ void mma16816(float c[4], const uint32_t a[4],
                                         uint32_t b0, uint32_t b1) {
    asm volatile("mma.sync.aligned.m16n8k16.row.col.f32.f16.f16.f32 "
                 "{%0,%1,%2,%3},{%4,%5,%6,%7},{%8,%9},{%0,%1,%2,%3};"
                 : "+f"(c[0]), "+f"(c[1]), "+f"(c[2]), "+f"(c[3])
                 : "r"(a[0]), "r"(a[1]), "r"(a[2]), "r"(a[3]), "r"(b0), "r"(b1));
}
#define CP16(dst, src) \
    asm volatile("cp.async.cg.shared.global [%0], [%1], 16;" :: "r"(dst), "l"(src))
#define CP_COMMIT() asm volatile("cp.async.commit_group;" ::: "memory")
#define CP_WAIT0()  asm volatile("cp.async.wait_group 0;" ::: "memory")

__device__ __forceinline__ void spin_until(unsigned* flag, unsigned target) {
    while (atomicAdd(flag, 0u) < target) __nanosleep(64);
}

// =====================================================================
// ONE kernel, two roles:
//   bids [0, 32):   HMMA KV projection -> g_k, g_v ; bump g_flag_kv
//   bids [32, 544): fused tile pipeline (inline fp32->fp16 weight staging;
//                   waits on g_flag_kv only, ~30us in)
// =====================================================================
__global__ __launch_bounds__(256, 2) void mega_kernel(
    const float* __restrict__ x,
    const float* __restrict__ prior,
    const float* __restrict__ g1, const float* __restrict__ b1,
    const float* __restrict__ g2, const float* __restrict__ b2,
    const float* __restrict__ Wq, const float* __restrict__ Wkv,
    const float* __restrict__ Wp, const float* __restrict__ bp,
    float* __restrict__ out)
{
    extern __shared__ char smraw[];
    const uint32_t SB = smem_u32(smraw);
    int tid  = threadIdx.x;
    int wid  = tid >> 5, lane = tid & 31;
    int gid  = lane >> 2, t4 = lane & 3;
    const uint32_t l15 = lane & 15;
    const uint32_t chalf = (lane >> 4) * 16;
    uint32_t* Wu = reinterpret_cast<uint32_t*>(smraw + O_KV);   // stride 100 u32

    // ================= role 1: KV projection =================
    if (blockIdx.x < NKV_BLK) {
        uint32_t* Au = reinterpret_cast<uint32_t*>(smraw + O_XQ);

        int kvb = (int)blockIdx.x;
        int b   = kvb >> 3;
        int m0  = ((kvb >> 2) & 1) * 128;
        int nq  = kvb & 3;

        const float2* psrc = reinterpret_cast<const float2*>(
            prior + (size_t)(b*MLEN + m0) * DIMC);
        for (int idx = tid; idx < 128*96; idx += 256) {
            float2 v = psrc[idx];
            Au[(idx / 96)*100 + (idx % 96)] = pack_h2(v.x, v.y);
        }
        __syncthreads();

        // LN in place
        {
            int row = tid >> 1, hf = tid & 1;
            float s = 0.f, s2 = 0.f;
            uint32_t vals[48];
            #pragma unroll
            for (int j = 0; j < 48; j++) {
                vals[j] = Au[row*100 + hf*48 + j];
                float2 f = __half22float2(*reinterpret_cast<__half2*>(&vals[j]));
                s += f.x + f.y;  s2 += f.x*f.x + f.y*f.y;
            }
            s  += __shfl_xor_sync(0xffffffffu, s, 1);
            s2 += __shfl_xor_sync(0xffffffffu, s2, 1);
            float mu   = s * (1.f/DIMC);
            float rstd = rsqrtf(s2*(1.f/DIMC) - mu*mu + 1e-5f);
            #pragma unroll
            for (int j = 0; j < 48; j++) {
                int k = hf*96 + 2*j;
                float2 f = __half22float2(*reinterpret_cast<__half2*>(&vals[j]));
                float v0 = (f.x - mu) * rstd * __ldg(g2 + k)     + __ldg(b2 + k);
                float v1 = (f.y - mu) * rstd * __ldg(g2 + k + 1) + __ldg(b2 + k + 1);
                Au[row*100 + hf*48 + j] = pack_h2(v0, v1);
            }
        }

        // GEMM [128x192] @ [192x96], two 96-row Wkv chunks (fp32 inline)
        int mw = wid >> 1, nw = wid & 1;
        float acc[2][6][4];
        #pragma unroll
        for (int mi = 0; mi < 2; mi++)
            #pragma unroll
            for (int j = 0; j < 6; j++)
                #pragma unroll
                for (int q = 0; q < 4; q++) acc[mi][j][q] = 0.f;

        uint32_t xa0 = SB + O_XQ + (mw*32 +      l15)*400 + chalf;
        uint32_t xa1 = SB + O_XQ + (mw*32 + 16 + l15)*400 + chalf;
        uint32_t wa  = SB + O_KV + l15*400 + chalf + nw*96;

        #pragma unroll
        for (int kc = 0; kc < 2; kc++) {
            __syncthreads();
            for (int idx = tid; idx < 96*48; idx += 256) {
                int r = idx / 48, cp = idx % 48;
                const float2* wsrc = reinterpret_cast<const float2*>(
                    Wkv + (size_t)(kc*96 + r)*384 + nq*96);
                float2 v = wsrc[cp];
                Wu[r*100 + cp] = pack_h2(v.x, v.y);
            }
            __syncthreads();

            #pragma unroll
            for (int ks = 0; ks < 6; ks++) {
                uint32_t a0[4], a1[4];
                ldsm4(a0, xa0 + kc*192 + ks*32);
                ldsm4(a1, xa1 + kc*192 + ks*32);
                #pragma unroll
                for (int j = 0; j < 3; j++) {
                    uint32_t bb[4];
                    ldsm4t(bb, wa + ks*16*400 + j*32);
                    mma16816(acc[0][2*j],   a0, bb[0], bb[1]);
                    mma16816(acc[0][2*j+1], a0, bb[2], bb[3]);
                    mma16816(acc[1][2*j],   a1, bb[0], bb[1]);
                    mma16816(acc[1][2*j+1], a1, bb[2], bb[3]);
                }
            }
        }

        uint32_t* dst = reinterpret_cast<uint32_t*>((nq < 2) ? g_k : g_v);
        int cbase = (nq & 1) * 48;
        #pragma unroll
        for (int mi = 0; mi < 2; mi++) {
            int r = mw*32 + mi*16 + gid;
            size_t row0 = (size_t)(b*MLEN + m0 + r) * 96;
            size_t row8 = row0 + 8*96;
            #pragma unroll
            for (int j = 0; j < 6; j++) {
                int cu = cbase + nw*24 + j*4 + t4;
                dst[row0 + cu] = pack_h2(acc[mi][j][0], acc[mi][j][1]);
                dst[row8 + cu] = pack_h2(acc[mi][j][2], acc[mi][j][3]);
            }
        }
        __threadfence();
        __syncthreads();
        if (tid == 0) atomicAdd(&g_flag_kv, 1u);
        return;
    }

    // ================= role 2: fused tile pipeline =================
    uint32_t* XQu = reinterpret_cast<uint32_t*>(smraw + O_XQ);   // stride 100 u32
    float*    bps = reinterpret_cast<float*>(smraw + O_BP);

    int fbid = (int)blockIdx.x - NKV_BLK;
    int b    = fbid >> 7;
    int n0   = (fbid & 127) * TILE;
    const size_t xbase = (size_t)b * DIMC * NTOK;

    const uint32_t l7  = lane & 7;
    const uint32_t mrow8 = ((lane >> 4) << 3);
    const uint32_t d8  = ((lane >> 3) & 1) * 16;

    // inline fp32 -> fp16 weight staging (96-row chunk, 400B stride)
    auto stage_w32 = [&](const float* W, int chunk, float scale) {
        const float2* src = reinterpret_cast<const float2*>(W + (size_t)chunk*96*192);
        #pragma unroll 4
        for (int idx = tid; idx < 96*96; idx += 256) {
            float2 v = src[idx];
            Wu[(idx / 96)*100 + (idx % 96)] = pack_h2(v.x * scale, v.y * scale);
        }
    };
    auto stage_k = [&](int h) {
        const char* ksrc = (const char*)(g_k + (size_t)b*MLEN*DIMC + h*HD);
        #pragma unroll
        for (int it = 0; it < 4; it++) {
            int idx = tid + it*256;
            int m = idx >> 2, ch = (idx & 3) * 16;
            CP16(SB + O_KV + m*80 + ch, ksrc + m*(DIMC*2) + ch);
        }
        CP_COMMIT();
    };
    auto stage_v = [&](int h) {
        const char* vsrc = (const char*)(g_v + (size_t)b*MLEN*DIMC + h*HD);
        #pragma unroll
        for (int it = 0; it < 4; it++) {
            int idx = tid + it*256;
            int m = idx >> 2, ch = (idx & 3) * 16;
            CP16(SB + O_V + m*80 + ch, vsrc + m*(DIMC*2) + ch);
        }
        CP_COMMIT();
    };

    for (int i = tid; i < DIMC; i += 256) bps[i] = bp[i];

    // ---------- phase 1: load x as fp16 into XQ, LN in place ----------
    for (int idx = tid; idx < TILE*(DIMC/2); idx += 256) {
        int cp = idx >> 7, i = idx & 127;
        float v0 = x[xbase + (size_t)(2*cp  )*NTOK + n0 + i];
        float v1 = x[xbase + (size_t)(2*cp+1)*NTOK + n0 + i];
        XQu[i*100 + cp] = pack_h2(v0, v1);
    }
    __syncthreads();
    {
        int row = tid >> 1, hf = tid & 1;
        float s = 0.f, s2 = 0.f;
        uint32_t vals[48];
        #pragma unroll
        for (int j = 0; j < 48; j++) {
            vals[j] = XQu[row*100 + hf*48 + j];
            float2 f = __half22float2(*reinterpret_cast<__half2*>(&vals[j]));
            s += f.x + f.y;  s2 += f.x*f.x + f.y*f.y;
        }
        s  += __shfl_xor_sync(0xffffffffu, s, 1);
        s2 += __shfl_xor_sync(0xffffffffu, s2, 1);
        float mu   = s * (1.f/DIMC);
        float rstd = rsqrtf(s2*(1.f/DIMC) - mu*mu + 1e-5f);
        #pragma unroll
        for (int j = 0; j < 48; j++) {
            int k = hf*96 + 2*j;
            float2 f = __half22float2(*reinterpret_cast<__half2*>(&vals[j]));
            float v0 = (f.x - mu) * rstd * __ldg(g1 + k)     + __ldg(b1 + k);
            float v1 = (f.y - mu) * rstd * __ldg(g1 + k + 1) + __ldg(b1 + k + 1);
            XQu[row*100 + hf*48 + j] = pack_h2(v0, v1);
        }
    }
    stage_w32(Wq, 0, QSCALE);
    __syncthreads();   // LN stores + Wq chunk 0 visible

    int mw = wid >> 1, nw = wid & 1;

    // ---------- phase 2: Qproj  Q = X @ Wq(scaled), 2 K-chunks ----------
    {
        float acc[2][12][4];
        #pragma unroll
        for (int mi = 0; mi < 2; mi++)
            #pragma unroll
            for (int j = 0; j < 12; j++)
                #pragma unroll
                for (int q = 0; q < 4; q++) acc[mi][j][q] = 0.f;

        uint32_t xa0 = SB + O_XQ + (mw*32 +      l15)*400 + chalf;
        uint32_t xa1 = SB + O_XQ + (mw*32 + 16 + l15)*400 + chalf;
        uint32_t wa  = SB + O_KV + l15*400 + chalf + nw*192;

        #pragma unroll
        for (int kc = 0; kc < 2; kc++) {
            #pragma unroll
            for (int ks = 0; ks < 6; ks++) {
                uint32_t a0[4], a1[4];
                ldsm4(a0, xa0 + kc*192 + ks*32);
                ldsm4(a1, xa1 + kc*192 + ks*32);
                #pragma unroll
                for (int j = 0; j < 6; j++) {
                    uint32_t bb[4];
                    ldsm4t(bb, wa + ks*16*400 + j*32);
                    mma16816(acc[0][2*j],   a0, bb[0], bb[1]);
                    mma16816(acc[0][2*j+1], a0, bb[2], bb[3]);
                    mma16816(acc[1][2*j],   a1, bb[0], bb[1]);
                    mma16816(acc[1][2*j+1], a1, bb[2], bb[3]);
                }
            }
            __syncthreads();
            if (kc == 0) {
                stage_w32(Wq, 1, QSCALE);
                __syncthreads();
            }
        }

        // K/V ready? (KV CTAs are ~10us; we're ~30us in — usually instant)
        if (tid == 0) spin_until(&g_flag_kv, NKV_BLK);
        __syncthreads();
        __threadfence();
        stage_k(0);
        stage_v(0);

        #pragma unroll
        for (int mi = 0; mi < 2; mi++) {
            int r = mw*32 + mi*16 + gid;
            #pragma unroll
            for (int j = 0; j < 12; j++) {
                int cu = nw*48 + j*4 + t4;
                XQu[r*100 + cu]       = pack_h2(acc[mi][j][0], acc[mi][j][1]);
                XQu[(r + 8)*100 + cu] = pack_h2(acc[mi][j][2], acc[mi][j][3]);
            }
        }
    }

    // ---------- phase 3: attention heads (flash-split, f16x2 softmax) ----------
    for (int h = 0; h < NH; h++) {
        CP_WAIT0();
        __syncthreads();   // K/V(h) + (h=0) Q stores visible

        uint32_t qa = SB + O_XQ + (wid*16 + l15)*400 + chalf + h*64;
        uint32_t qf[2][4];
        ldsm4(qf[0], qa);
        ldsm4(qf[1], qa + 32);

        float oc[4][4];
        #pragma unroll
        for (int n = 0; n < 4; n++)
            #pragma unroll
            for (int q = 0; q < 4; q++) oc[n][q] = 0.f;
        float mxl = -1e30f, mxh = -1e30f, sl = 0.f, sh = 0.f;

        #pragma unroll
        for (int half = 0; half < 2; half++) {
            float sa[16][4];
            #pragma unroll
            for (int n = 0; n < 16; n++)
                #pragma unroll
                for (int q = 0; q < 4; q++) sa[n][q] = 0.f;

            uint32_t ka = SB + O_KV + (half*128 + l7 + mrow8)*80 + d8;
            #pragma unroll
            for (int ks = 0; ks < 2; ks++) {
                #pragma unroll
                for (int jm = 0; jm < 8; jm++) {
                    uint32_t bb[4];
                    ldsm4(bb, ka + jm*16*80 + ks*32);
                    mma16816(sa[2*jm],   qf[ks], bb[0], bb[1]);
                    mma16816(sa[2*jm+1], qf[ks], bb[2], bb[3]);
                }
            }

            if (half == 1) {
                __syncthreads();
                if (h + 1 < NH) stage_k(h + 1);
            }

            float cml = -1e30f, cmh = -1e30f;
            #pragma unroll
            for (int n = 0; n < 16; n++) {
                cml = fmaxf(cml, fmaxf(sa[n][0], sa[n][1]));
                cmh = fmaxf(cmh, fmaxf(sa[n][2], sa[n][3]));
            }
            cml = fmaxf(cml, __shfl_xor_sync(0xffffffffu, cml, 1));
            cml = fmaxf(cml, __shfl_xor_sync(0xffffffffu, cml, 2));
            cmh = fmaxf(cmh, __shfl_xor_sync(0xffffffffu, cmh, 1));
            cmh = fmaxf(cmh, __shfl_xor_sync(0xffffffffu, cmh, 2));
            float nml = fmaxf(mxl, cml), nmh = fmaxf(mxh, cmh);
            float fl = ex2f(mxl - nml), fh = ex2f(mxh - nmh);
            mxl = nml; mxh = nmh;

            uint32_t pe[16][2];
            float csl = 0.f, csh = 0.f;
            #pragma unroll
            for (int n = 0; n < 16; n++) {
                pe[n][0] = ex2_h2(pack_h2(sa[n][0] - nml, sa[n][1] - nml));
                pe[n][1] = ex2_h2(pack_h2(sa[n][2] - nmh, sa[n][3] - nmh));
                float2 e0 = __half22float2(*reinterpret_cast<__half2*>(&pe[n][0]));
                float2 e1 = __half22float2(*reinterpret_cast<__half2*>(&pe[n][1]));
                csl += e0.x + e0.y;
                csh += e1.x + e1.y;
            }
            csl += __shfl_xor_sync(0xffffffffu, csl, 1);
            csl += __shfl_xor_sync(0xffffffffu, csl, 2);
            csh += __shfl_xor_sync(0xffffffffu, csh, 1);
            csh += __shfl_xor_sync(0xffffffffu, csh, 2);
            sl = sl*fl + csl;
            sh = sh*fh + csh;
            #pragma unroll
            for (int n = 0; n < 4; n++) {
                oc[n][0] *= fl; oc[n][1] *= fl;
                oc[n][2] *= fh; oc[n][3] *= fh;
            }

            uint32_t va = SB + O_V + (half*128 + l15)*80 + chalf;
            #pragma unroll
            for (int kt = 0; kt < 8; kt++) {
                uint32_t a[4];
                a[0] = pe[2*kt][0];
                a[1] = pe[2*kt][1];
                a[2] = pe[2*kt+1][0];
                a[3] = pe[2*kt+1][1];
                #pragma unroll
                for (int j = 0; j < 2; j++) {
                    uint32_t bb[4];
                    ldsm4t(bb, va + kt*16*80 + j*32);
                    mma16816(oc[2*j],   a, bb[0], bb[1]);
                    mma16816(oc[2*j+1], a, bb[2], bb[3]);
                }
            }
        }

        float il = 1.f / sl, ih = 1.f / sh;
        int rl = wid*16 + gid;
        #pragma unroll
        for (int n = 0; n < 4; n++) {
            XQu[rl*100     + h*16 + n*4 + t4] = pack_h2(oc[n][0]*il, oc[n][1]*il);
            XQu[(rl+8)*100 + h*16 + n*4 + t4] = pack_h2(oc[n][2]*ih, oc[n][3]*ih);
        }
        __syncthreads();   // V reads done before restage / W overwrite
        if (h + 1 < NH) stage_v(h + 1);
    }

    // ---------- phase 4: outproj (2 K-chunks, inline Wp) + epilogue ----------
    {
        stage_w32(Wp, 0, 1.0f);
        __syncthreads();   // Wp chunk 0 + all O stores visible

        float acc[2][12][4];
        #pragma unroll
        for (int mi = 0; mi < 2; mi++)
            #pragma unroll
            for (int j = 0; j < 12; j++)
                #pragma unroll
                for (int q = 0; q < 4; q++) acc[mi][j][q] = 0.f;

        uint32_t xa0 = SB + O_XQ + (mw*32 +      l15)*400 + chalf;
        uint32_t xa1 = SB + O_XQ + (mw*32 + 16 + l15)*400 + chalf;
        uint32_t wa  = SB + O_KV + l15*400 + chalf + nw*192;

        #pragma unroll
        for (int kc = 0; kc < 2; kc++) {
            #pragma unroll
            for (int ks = 0; ks < 6; ks++) {
                uint32_t a0[4], a1[4];
                ldsm4(a0, xa0 + kc*192 + ks*32);
                ldsm4(a1, xa1 + kc*192 + ks*32);
                #pragma unroll
                for (int j = 0; j < 6; j++) {
                    uint32_t bb[4];
                    ldsm4t(bb, wa + ks*16*400 + j*32);
                    mma16816(acc[0][2*j],   a0, bb[0], bb[1]);
                    mma16816(acc[0][2*j+1], a0, bb[2], bb[3]);
                    mma16816(acc[1][2*j],   a1, bb[0], bb[1]);
                    mma16816(acc[1][2*j+1], a1, bb[2], bb[3]);
                }
            }
            if (kc == 0) {
                __syncthreads();
                stage_w32(Wp, 1, 1.0f);
                __syncthreads();
            }
        }

        #pragma unroll
        for (int mi = 0; mi < 2; mi++) {
            int r = mw*32 + mi*16 + gid;
            #pragma unroll
            for (int j = 0; j < 12; j++) {
                int c = nw*96 + j*8 + t4*2;
                size_t g0  = xbase + (size_t)c*NTOK + n0 + r;
                size_t g1a = g0 + NTOK;
                out[g0]      = acc[mi][j][0] + bps[c]     + __ldg(x + g0);
                out[g1a]     = acc[mi][j][1] + bps[c + 1] + __ldg(x + g1a);
                out[g0 + 8]  = acc[mi][j][2] + bps[c]     + __ldg(x + g0 + 8);
                out[g1a + 8] = acc[mi][j][3] + bps[c + 1] + __ldg(x + g1a + 8);
            }
        }
    }
}

// =====================================================================
extern "C" void kernel_launch(void* const* d_in, const int* in_sizes, int n_in,
                              void* d_out, int out_size)
{
    (void)in_sizes; (void)n_in; (void)out_size;
    const float* x     = (const float*)d_in[0];
    const float* prior = (const float*)d_in[1];
    const float* ln1_g = (const float*)d_in[2];
    const float* ln1_b = (const float*)d_in[3];
    const float* ln2_g = (const float*)d_in[4];
    const float* ln2_b = (const float*)d_in[5];
    const float* Wq    = (const float*)d_in[6];
    const float* Wkv   = (const float*)d_in[7];
    const float* Wp    = (const float*)d_in[8];
    const float* bp    = (const float*)d_in[9];
    float* out = (float*)d_out;

    cudaFuncSetAttribute(mega_kernel, cudaFuncAttributeMaxDynamicSharedMemorySize, SMEM_BYTES);
    mega_kernel<<<NKV_BLK + BATCH * (NTOK/TILE), 256, SMEM_BYTES>>>(
        x, prior, ln1_g, ln1_b, ln2_g, ln2_b, Wq, Wkv, Wp, bp, out);
}

// round 16
// speedup vs baseline: 1.3439x; 1.1181x over previous
#include <cuda_runtime.h>
#include <cuda_fp16.h>
#include <cstdint>

#define DIMC   192
#define NH     6
#define HD     32
#define MLEN   256
#define NTOK   16384
#define BATCH  4
#define TILE   128

// softmax scale * log2(e), folded into Wq
#define QSCALE 0.25504157602086453f

// ---- device-global scratch (no runtime allocation allowed) ----
__device__ __half g_k [BATCH * MLEN * DIMC];   // [b][m][c] fp16
__device__ __half g_v [BATCH * MLEN * DIMC];   // [b][m][c] fp16
__device__ __half g_wq[DIMC * DIMC];           // Wq * QSCALE, row-major [k][n]
__device__ __half g_wp[DIMC * DIMC];           // Wp, row-major [k][n]

// ---------------- fused kernel smem byte offsets ----------------
#define O_XQ   0            // X -> Q -> O: fp16 [128] rows, 400B stride (51200)
#define O_KV   51200        // union: W chunk [96]x400B (38400) | K [256]x80B + V [256]x80B
#define O_V    71680        // V = O_KV + 20480
#define O_BP   92160        // bias fp32 [192]
#define SMEM_BYTES (O_BP + 768 + 256)   // 93184  (2 CTAs/SM)

// ---------------- kv kernel smem (64 CTAs, 1 CTA/SM) ----------------
#define O2_A   0            // LN(prior) fp16 [64] rows, 400B stride (25600)
#define O2_W   25600        // Wkv quarter fp16 [192] rows, 400B stride (76800)
#define SMEM2_BYTES (O2_W + 76800 + 256)   // ~100 KB

#define NKV_BLK 64

// ========================= helpers =========================
__device__ __forceinline__ uint32_t smem_u32(const void* p) {
    uint32_t a;
    asm("{ .reg .u64 t; cvta.to.shared.u64 t, %1; cvt.u32.u64 %0, t; }" : "=r"(a) : "l"(p));
    return a;
}
__device__ __forceinline__ float ex2f(float x) {
    float r; asm("ex2.approx.f32 %0, %1;" : "=f"(r) : "f"(x)); return r;
}
__device__ __forceinline__ uint32_t ex2_h2(uint32_t x) {
    uint32_t r; asm("ex2.approx.f16x2 %0, %1;" : "=r"(r) : "r"(x)); return r;
}
__device__ __forceinline__ uint32_t pack_h2(float lo, float hi) {
    uint32_t r; asm("cvt.rn.f16x2.f32 %0, %1, %2;" : "=r"(r) : "f"(hi), "f"(lo)); return r;
}
__device__ __forceinline__ void ldsm4(uint32_t r[4], uint32_t addr) {
    asm volatile("ldmatrix.sync.aligned.m8n8.x4.shared.b16 {%0,%1,%2,%3}, [%4];"
                 : "=r"(r[0]), "=r"(r[1]), "=r"(r[2]), "=r"(r[3]) : "r"(addr));
}
__device__ __forceinline__ void ldsm4t(uint32_t r[4], uint32_t addr) {
    asm volatile("ldmatrix.sync.aligned.m8n8.x4.trans.shared.b16 {%0,%1,%2,%3}, [%4];"
                 : "=r"(r[0]), "=r"(r[1]), "=r"(r[2]), "=r"(r[3]) : "r"(addr));
}
__device__ __forceinline__ void mma16816(float c[4], const uint32_t a[4],
                                         uint32_t b0, uint32_t b1) {
    asm volatile("mma.sync.aligned.m16n8k16.row.col.f32.f16.f16.f32 "
                 "{%0,%1,%2,%3},{%4,%5,%6,%7},{%8,%9},{%0,%1,%2,%3};"
                 : "+f"(c[0]), "+f"(c[1]), "+f"(c[2]), "+f"(c[3])
                 : "r"(a[0]), "r"(a[1]), "r"(a[2]), "r"(a[3]), "r"(b0), "r"(b1));
}
#define CP16(dst, src) \
    asm volatile("cp.async.cg.shared.global [%0], [%1], 16;" :: "r"(dst), "l"(src))
#define CP_COMMIT() asm volatile("cp.async.commit_group;" ::: "memory")
#define CP_WAIT0()  asm volatile("cp.async.wait_group 0;" ::: "memory")
#define CP_WAIT1()  asm volatile("cp.async.wait_group 1;" ::: "memory")

// =====================================================================
// Kernel 1 (merged):
//   blocks [0,64):    HMMA KV projection. block = (b, mtile64, nquarter96).
//                     out[64x96] = LN(prior tile) @ Wkv[:, nq*96 .. +96]
//   blocks [64,136):  weight prep -> g_wq (scaled), g_wp
// =====================================================================
__global__ __launch_bounds__(256) void prep_kv_kernel(
    const float* __restrict__ prior,
    const float* __restrict__ g2, const float* __restrict__ b2,
    const float* __restrict__ Wkv,
    const float* __restrict__ Wq, const float* __restrict__ Wp)
{
    int tid = threadIdx.x;

    if (blockIdx.x >= NKV_BLK) {
        // ---- weight prep: 72 blocks x 512 items ----
        int base = (int)(blockIdx.x - NKV_BLK) * 512 + tid;
        #pragma unroll
        for (int it = 0; it < 2; it++) {
            int idx = base + it*256;
            g_wq[idx] = __float2half_rn(Wq[idx] * QSCALE);
            g_wp[idx] = __float2half_rn(Wp[idx]);
        }
        return;
    }

    extern __shared__ char smraw2[];
    const uint32_t SB = smem_u32(smraw2);
    uint32_t* Au = reinterpret_cast<uint32_t*>(smraw2 + O2_A);   // stride 100 u32
    uint32_t* Wu = reinterpret_cast<uint32_t*>(smraw2 + O2_W);   // stride 100 u32

    int kvb = (int)blockIdx.x;
    int b   = kvb >> 4;                 // 16 blocks per batch
    int m0  = ((kvb >> 2) & 3) * 64;    // 4 m-tiles of 64 rows
    int nq  = kvb & 3;                  // 4 n-quarters of 96 cols

    int wid = tid >> 5, lane = tid & 31;
    int gid = lane >> 2, t4 = lane & 3;
    const uint32_t l15 = lane & 15;
    const uint32_t chalf = (lane >> 4) * 16;

    // issue prior tile loads (64x192 fp32 -> fp16) and Wkv quarter loads
    const float2* psrc = reinterpret_cast<const float2*>(
        prior + (size_t)(b*MLEN + m0) * DIMC);
    for (int idx = tid; idx < 64*96; idx += 256) {
        float2 v = psrc[idx];
        Au[(idx / 96)*100 + (idx % 96)] = pack_h2(v.x, v.y);
    }
    for (int idx = tid; idx < 192*48; idx += 256) {
        int r = idx / 48, cp = idx % 48;
        const float2* wsrc = reinterpret_cast<const float2*>(
            Wkv + (size_t)r*384 + nq*96);
        float2 v = wsrc[cp];
        Wu[r*100 + cp] = pack_h2(v.x, v.y);
    }
    __syncthreads();

    // LN in place: 4 threads per row, 48 fp16 (24 u32) each
    {
        int row = tid >> 2, part = tid & 3;
        float s = 0.f, s2 = 0.f;
        uint32_t vals[24];
        #pragma unroll
        for (int j = 0; j < 24; j++) {
            vals[j] = Au[row*100 + part*24 + j];
            float2 f = __half22float2(*reinterpret_cast<__half2*>(&vals[j]));
            s += f.x + f.y;  s2 += f.x*f.x + f.y*f.y;
        }
        s  += __shfl_xor_sync(0xffffffffu, s, 1);
        s  += __shfl_xor_sync(0xffffffffu, s, 2);
        s2 += __shfl_xor_sync(0xffffffffu, s2, 1);
        s2 += __shfl_xor_sync(0xffffffffu, s2, 2);
        float mu   = s * (1.f/DIMC);
        float rstd = rsqrtf(s2*(1.f/DIMC) - mu*mu + 1e-5f);
        #pragma unroll
        for (int j = 0; j < 24; j++) {
            int k = part*48 + 2*j;
            float2 f = __half22float2(*reinterpret_cast<__half2*>(&vals[j]));
            float v0 = (f.x - mu) * rstd * __ldg(g2 + k)     + __ldg(b2 + k);
            float v1 = (f.y - mu) * rstd * __ldg(g2 + k + 1) + __ldg(b2 + k + 1);
            Au[row*100 + part*24 + j] = pack_h2(v0, v1);
        }
    }
    __syncthreads();

    // GEMM [64x192] @ [192x96]; warp = 16 rows x 48 cols (4m x 2n warp grid)
    int mw = wid >> 1, nw = wid & 1;
    float acc[6][4];
    #pragma unroll
    for (int j = 0; j < 6; j++)
        #pragma unroll
        for (int q = 0; q < 4; q++) acc[j][q] = 0.f;

    uint32_t xa = SB + O2_A + (mw*16 + l15)*400 + chalf;
    uint32_t wa = SB + O2_W + l15*400 + chalf + nw*96;

    #pragma unroll
    for (int ks = 0; ks < 12; ks++) {
        uint32_t a[4];
        ldsm4(a, xa + ks*32);
        #pragma unroll
        for (int j = 0; j < 3; j++) {
            uint32_t bb[4];
            ldsm4t(bb, wa + ks*16*400 + j*32);
            mma16816(acc[2*j],   a, bb[0], bb[1]);
            mma16816(acc[2*j+1], a, bb[2], bb[3]);
        }
    }

    // store fragments as packed fp16 to g_k / g_v
    uint32_t* dst = reinterpret_cast<uint32_t*>((nq < 2) ? g_k : g_v);
    int cbase = (nq & 1) * 48;
    {
        int r = mw*16 + gid;
        size_t row0 = (size_t)(b*MLEN + m0 + r) * 96;
        size_t row8 = row0 + 8*96;
        #pragma unroll
        for (int j = 0; j < 6; j++) {
            int cu = cbase + nw*24 + j*4 + t4;
            dst[row0 + cu] = pack_h2(acc[j][0], acc[j][1]);
            dst[row8 + cu] = pack_h2(acc[j][2], acc[j][3]);
        }
    }
}

// =====================================================================
// Kernel 2: fused LN -> Qproj -> attention -> outproj -> residual
// R13 base + split K/V cp.async waits (V latency hidden behind softmax).
// =====================================================================
__global__ __launch_bounds__(256, 2) void fused_kernel(
    const float* __restrict__ x,
    const float* __restrict__ g1, const float* __restrict__ b1,
    const float* __restrict__ bp, float* __restrict__ out)
{
    extern __shared__ char smraw[];
    const uint32_t SB = smem_u32(smraw);
    uint32_t* XQu = reinterpret_cast<uint32_t*>(smraw + O_XQ);   // stride 100 u32
    float*    bps = reinterpret_cast<float*>(smraw + O_BP);

    int tid  = threadIdx.x;
    int wid  = tid >> 5, lane = tid & 31;
    int gid  = lane >> 2, t4 = lane & 3;
    int b    = blockIdx.x >> 7;
    int n0   = (blockIdx.x & 127) * TILE;
    const size_t xbase = (size_t)b * DIMC * NTOK;

    const uint32_t l15 = lane & 15;
    const uint32_t chalf = (lane >> 4) * 16;
    const uint32_t l7  = lane & 7;
    const uint32_t mrow8 = ((lane >> 4) << 3);
    const uint32_t d8  = ((lane >> 3) & 1) * 16;

    auto stage_w = [&](const __half* W, int chunk) {
        const char* src = (const char*)W + chunk*96*384;
        #pragma unroll
        for (int it = 0; it < 9; it++) {
            int idx = tid + it*256;
            int r = idx / 24, ch = (idx % 24) * 16;
            CP16(SB + O_KV + r*400 + ch, src + r*384 + ch);
        }
        CP_COMMIT();
    };
    auto stage_k = [&](int h) {
        const char* ksrc = (const char*)(g_k + (size_t)b*MLEN*DIMC + h*HD);
        #pragma unroll
        for (int it = 0; it < 4; it++) {
            int idx = tid + it*256;
            int m = idx >> 2, ch = (idx & 3) * 16;
            CP16(SB + O_KV + m*80 + ch, ksrc + m*(DIMC*2) + ch);
        }
        CP_COMMIT();
    };
    auto stage_v = [&](int h) {
        const char* vsrc = (const char*)(g_v + (size_t)b*MLEN*DIMC + h*HD);
        #pragma unroll
        for (int it = 0; it < 4; it++) {
            int idx = tid + it*256;
            int m = idx >> 2, ch = (idx & 3) * 16;
            CP16(SB + O_V + m*80 + ch, vsrc + m*(DIMC*2) + ch);
        }
        CP_COMMIT();
    };

    stage_w(g_wq, 0);    // prefetch Wq chunk 0 under x-load + LN
    for (int i = tid; i < DIMC; i += 256) bps[i] = bp[i];

    // ---------- phase 1: load x as fp16 into XQ, LN in place ----------
    for (int idx = tid; idx < TILE*(DIMC/2); idx += 256) {
        int cp = idx >> 7, i = idx & 127;
        float v0 = x[xbase + (size_t)(2*cp  )*NTOK + n0 + i];
        float v1 = x[xbase + (size_t)(2*cp+1)*NTOK + n0 + i];
        XQu[i*100 + cp] = pack_h2(v0, v1);
    }
    __syncthreads();
    {
        int row = tid >> 1, hf = tid & 1;
        float s = 0.f, s2 = 0.f;
        uint32_t vals[48];
        #pragma unroll
        for (int j = 0; j < 48; j++) {
            vals[j] = XQu[row*100 + hf*48 + j];
            float2 f = __half22float2(*reinterpret_cast<__half2*>(&vals[j]));
            s += f.x + f.y;  s2 += f.x*f.x + f.y*f.y;
        }
        s  += __shfl_xor_sync(0xffffffffu, s, 1);
        s2 += __shfl_xor_sync(0xffffffffu, s2, 1);
        float mu   = s * (1.f/DIMC);
        float rstd = rsqrtf(s2*(1.f/DIMC) - mu*mu + 1e-5f);
        #pragma unroll
        for (int j = 0; j < 48; j++) {
            int k = hf*96 + 2*j;
            float2 f = __half22float2(*reinterpret_cast<__half2*>(&vals[j]));
            float v0 = (f.x - mu) * rstd * __ldg(g1 + k)     + __ldg(b1 + k);
            float v1 = (f.y - mu) * rstd * __ldg(g1 + k + 1) + __ldg(b1 + k + 1);
            XQu[row*100 + hf*48 + j] = pack_h2(v0, v1);
        }
    }
    CP_WAIT0();
    __syncthreads();   // LN stores + Wq chunk 0 visible

    int mw = wid >> 1, nw = wid & 1;

    // ---------- phase 2: Qproj  Q = X @ Wq(scaled), 2 K-chunks ----------
    {
        float acc[2][12][4];
        #pragma unroll
        for (int mi = 0; mi < 2; mi++)
            #pragma unroll
            for (int j = 0; j < 12; j++)
                #pragma unroll
                for (int q = 0; q < 4; q++) acc[mi][j][q] = 0.f;

        uint32_t xa0 = SB + O_XQ + (mw*32 +      l15)*400 + chalf;
        uint32_t xa1 = SB + O_XQ + (mw*32 + 16 + l15)*400 + chalf;
        uint32_t wa  = SB + O_KV + l15*400 + chalf + nw*192;

        #pragma unroll
        for (int kc = 0; kc < 2; kc++) {
            #pragma unroll
            for (int ks = 0; ks < 6; ks++) {
                uint32_t a0[4], a1[4];
                ldsm4(a0, xa0 + kc*192 + ks*32);
                ldsm4(a1, xa1 + kc*192 + ks*32);
                #pragma unroll
                for (int j = 0; j < 6; j++) {
                    uint32_t bb[4];
                    ldsm4t(bb, wa + ks*16*400 + j*32);
                    mma16816(acc[0][2*j],   a0, bb[0], bb[1]);
                    mma16816(acc[0][2*j+1], a0, bb[2], bb[3]);
                    mma16816(acc[1][2*j],   a1, bb[0], bb[1]);
                    mma16816(acc[1][2*j+1], a1, bb[2], bb[3]);
                }
            }
            __syncthreads();
            if (kc == 0) {
                stage_w(g_wq, 1);
                CP_WAIT0();
                __syncthreads();
            }
        }

        stage_k(0);   // group: K(0)
        stage_v(0);   // group: V(0)

        #pragma unroll
        for (int mi = 0; mi < 2; mi++) {
            int r = mw*32 + mi*16 + gid;
            #pragma unroll
            for (int j = 0; j < 12; j++) {
                int cu = nw*48 + j*4 + t4;
                XQu[r*100 + cu]       = pack_h2(acc[mi][j][0], acc[mi][j][1]);
                XQu[(r + 8)*100 + cu] = pack_h2(acc[mi][j][2], acc[mi][j][3]);
            }
        }
    }

    // ---------- phase 3: attention heads (flash-split, split K/V waits) ----------
    for (int h = 0; h < NH; h++) {
        // K(h) is the oldest pending group; V(h) may still be in flight.
        CP_WAIT1();
        __syncthreads();   // K(h) + (h=0) Q stores visible

        uint32_t qa = SB + O_XQ + (wid*16 + l15)*400 + chalf + h*64;
        uint32_t qf[2][4];
        ldsm4(qf[0], qa);
        ldsm4(qf[1], qa + 32);

        float oc[4][4];
        #pragma unroll
        for (int n = 0; n < 4; n++)
            #pragma unroll
            for (int q = 0; q < 4; q++) oc[n][q] = 0.f;
        float mxl = -1e30f, mxh = -1e30f, sl = 0.f, sh = 0.f;

        #pragma unroll
        for (int half = 0; half < 2; half++) {
            float sa[16][4];
            #pragma unroll
            for (int n = 0; n < 16; n++)
                #pragma unroll
                for (int q = 0; q < 4; q++) sa[n][q] = 0.f;

            uint32_t ka = SB + O_KV + (half*128 + l7 + mrow8)*80 + d8;
            #pragma unroll
            for (int ks = 0; ks < 2; ks++) {
                #pragma unroll
                for (int jm = 0; jm < 8; jm++) {
                    uint32_t bb[4];
                    ldsm4(bb, ka + jm*16*80 + ks*32);
                    mma16816(sa[2*jm],   qf[ks], bb[0], bb[1]);
                    mma16816(sa[2*jm+1], qf[ks], bb[2], bb[3]);
                }
            }

            if (half == 1) {
                __syncthreads();   // all K(h) reads done
                if (h + 1 < NH) stage_k(h + 1);
            }

            float cml = -1e30f, cmh = -1e30f;
            #pragma unroll
            for (int n = 0; n < 16; n++) {
                cml = fmaxf(cml, fmaxf(sa[n][0], sa[n][1]));
                cmh = fmaxf(cmh, fmaxf(sa[n][2], sa[n][3]));
            }
            cml = fmaxf(cml, __shfl_xor_sync(0xffffffffu, cml, 1));
            cml = fmaxf(cml, __shfl_xor_sync(0xffffffffu, cml, 2));
            cmh = fmaxf(cmh, __shfl_xor_sync(0xffffffffu, cmh, 1));
            cmh = fmaxf(cmh, __shfl_xor_sync(0xffffffffu, cmh, 2));
            float nml = fmaxf(mxl, cml), nmh = fmaxf(mxh, cmh);
            float fl = ex2f(mxl - nml), fh = ex2f(mxh - nmh);
            mxl = nml; mxh = nmh;

            uint32_t pe[16][2];
            float csl = 0.f, csh = 0.f;
            #pragma unroll
            for (int n = 0; n < 16; n++) {
                pe[n][0] = ex2_h2(pack_h2(sa[n][0] - nml, sa[n][1] - nml));
                pe[n][1] = ex2_h2(pack_h2(sa[n][2] - nmh, sa[n][3] - nmh));
                float2 e0 = __half22float2(*reinterpret_cast<__half2*>(&pe[n][0]));
                float2 e1 = __half22float2(*reinterpret_cast<__half2*>(&pe[n][1]));
                csl += e0.x + e0.y;
                csh += e1.x + e1.y;
            }
            csl += __shfl_xor_sync(0xffffffffu, csl, 1);
            csl += __shfl_xor_sync(0xffffffffu, csl, 2);
            csh += __shfl_xor_sync(0xffffffffu, csh, 1);
            csh += __shfl_xor_sync(0xffffffffu, csh, 2);
            sl = sl*fl + csl;
            sh = sh*fh + csh;
            #pragma unroll
            for (int n = 0; n < 4; n++) {
                oc[n][0] *= fl; oc[n][1] *= fl;
                oc[n][2] *= fh; oc[n][3] *= fh;
            }

            // first V read of this head: ensure V(h) landed (had S-mma+softmax
            // of half 0 to hide its latency)
            if (half == 0) {
                CP_WAIT0();        // only V(h) pending at this point
                __syncthreads();
            }

            uint32_t va = SB + O_V + (half*128 + l15)*80 + chalf;
            #pragma unroll
            for (int kt = 0; kt < 8; kt++) {
                uint32_t a[4];
                a[0] = pe[2*kt][0];
                a[1] = pe[2*kt][1];
                a[2] = pe[2*kt+1][0];
                a[3] = pe[2*kt+1][1];
                #pragma unroll
                for (int j = 0; j < 2; j++) {
                    uint32_t bb[4];
                    ldsm4t(bb, va + kt*16*80 + j*32);
                    mma16816(oc[2*j],   a, bb[0], bb[1]);
                    mma16816(oc[2*j+1], a, bb[2], bb[3]);
                }
            }
        }

        float il = 1.f / sl, ih = 1.f / sh;
        int rl = wid*16 + gid;
        #pragma unroll
        for (int n = 0; n < 4; n++) {
            XQu[rl*100     + h*16 + n*4 + t4] = pack_h2(oc[n][0]*il, oc[n][1]*il);
            XQu[(rl+8)*100 + h*16 + n*4 + t4] = pack_h2(oc[n][2]*ih, oc[n][3]*ih);
        }
        __syncthreads();   // V reads done before restage
        if (h + 1 < NH) stage_v(h + 1);
        else            stage_w(g_wp, 0);
    }

    // ---------- phase 4: outproj (2 K-chunks) + direct epilogue ----------
    {
        CP_WAIT0();
        __syncthreads();   // Wp chunk 0 + all O stores visible

        float acc[2][12][4];
        #pragma unroll
        for (int mi = 0; mi < 2; mi++)
            #pragma unroll
            for (int j = 0; j < 12; j++)
                #pragma unroll
                for (int q = 0; q < 4; q++) acc[mi][j][q] = 0.f;

        uint32_t xa0 = SB + O_XQ + (mw*32 +      l15)*400 + chalf;
        uint32_t xa1 = SB + O_XQ + (mw*32 + 16 + l15)*400 + chalf;
        uint32_t wa  = SB + O_KV + l15*400 + chalf + nw*192;

        #pragma unroll
        for (int kc = 0; kc < 2; kc++) {
            #pragma unroll
            for (int ks = 0; ks < 6; ks++) {
                uint32_t a0[4], a1[4];
                ldsm4(a0, xa0 + kc*192 + ks*32);
                ldsm4(a1, xa1 + kc*192 + ks*32);
                #pragma unroll
                for (int j = 0; j < 6; j++) {
                    uint32_t bb[4];
                    ldsm4t(bb, wa + ks*16*400 + j*32);
                    mma16816(acc[0][2*j],   a0, bb[0], bb[1]);
                    mma16816(acc[0][2*j+1], a0, bb[2], bb[3]);
                    mma16816(acc[1][2*j],   a1, bb[0], bb[1]);
                    mma16816(acc[1][2*j+1], a1, bb[2], bb[3]);
                }
            }
            if (kc == 0) {
                __syncthreads();
                stage_w(g_wp, 1);
                CP_WAIT0();
                __syncthreads();
            }
        }

        #pragma unroll
        for (int mi = 0; mi < 2; mi++) {
            int r = mw*32 + mi*16 + gid;
            #pragma unroll
            for (int j = 0; j < 12; j++) {
                int c = nw*96 + j*8 + t4*2;
                size_t g0  = xbase + (size_t)c*NTOK + n0 + r;
                size_t g1a = g0 + NTOK;
                out[g0]      = acc[mi][j][0] + bps[c]     + __ldg(x + g0);
                out[g1a]     = acc[mi][j][1] + bps[c + 1] + __ldg(x + g1a);
                out[g0 + 8]  = acc[mi][j][2] + bps[c]     + __ldg(x + g0 + 8);
                out[g1a + 8] = acc[mi][j][3] + bps[c + 1] + __ldg(x + g1a + 8);
            }
        }
    }
}

// =====================================================================
extern "C" void kernel_launch(void* const* d_in, const int* in_sizes, int n_in,
                              void* d_out, int out_size)
{
    (void)in_sizes; (void)n_in; (void)out_size;
    const float* x     = (const float*)d_in[0];
    const float* prior = (const float*)d_in[1];
    const float* ln1_g = (const float*)d_in[2];
    const float* ln1_b = (const float*)d_in[3];
    const float* ln2_g = (const float*)d_in[4];
    const float* ln2_b = (const float*)d_in[5];
    const float* Wq    = (const float*)d_in[6];
    const float* Wkv   = (const float*)d_in[7];
    const float* Wp    = (const float*)d_in[8];
    const float* bp    = (const float*)d_in[9];
    float* out = (float*)d_out;

    cudaFuncSetAttribute(prep_kv_kernel, cudaFuncAttributeMaxDynamicSharedMemorySize, SMEM2_BYTES);
    cudaFuncSetAttribute(fused_kernel,   cudaFuncAttributeMaxDynamicSharedMemorySize, SMEM_BYTES);

    prep_kv_kernel<<<NKV_BLK + 72, 256, SMEM2_BYTES>>>(prior, ln2_g, ln2_b, Wkv, Wq, Wp);
    fused_kernel<<<BATCH * (NTOK/TILE), 256, SMEM_BYTES>>>(x, ln1_g, ln1_b, bp, out);
}

// round 17
// speedup vs baseline: 1.4461x; 1.0761x over previous
#include <cuda_runtime.h>
#include <cuda_fp16.h>
#include <cstdint>

#define DIMC   192
#define NH     6
#define HD     32
#define MLEN   256
#define NTOK   16384
#define BATCH  4
#define TILE   64
#define THREADS 128

// softmax scale * log2(e), folded into Wq
#define QSCALE 0.25504157602086453f

// ---- device-global scratch (no runtime allocation allowed) ----
__device__ __half g_k [BATCH * MLEN * DIMC];   // [b][m][c] fp16
__device__ __half g_v [BATCH * MLEN * DIMC];   // [b][m][c] fp16
__device__ __half g_wq[DIMC * DIMC];           // Wq * QSCALE, row-major [k][n]
__device__ __half g_wp[DIMC * DIMC];           // Wp, row-major [k][n]

// ---------------- fused kernel smem byte offsets ----------------
#define O_XQ   0            // X -> Q -> O: fp16 [64] rows, 400B stride (25600)
#define O_KV   25600        // union: W chunk [96]x400B (38400) | K [256]x80B + V [256]x80B
#define O_V    46080        // V = O_KV + 20480
#define O_BP   66560        // bias fp32 [192]
#define SMEM_BYTES (O_BP + 768 + 128)   // 67456  -> 3 CTAs/SM

// ---------------- kv kernel smem (64 CTAs, 1 CTA/SM) ----------------
#define O2_A   0            // LN(prior) fp16 [64] rows, 400B stride (25600)
#define O2_W   25600        // Wkv quarter fp16 [192] rows, 400B stride (76800)
#define SMEM2_BYTES (O2_W + 76800 + 256)

#define NKV_BLK 64

// ========================= helpers =========================
__device__ __forceinline__ uint32_t smem_u32(const void* p) {
    uint32_t a;
    asm("{ .reg .u64 t; cvta.to.shared.u64 t, %1; cvt.u32.u64 %0, t; }" : "=r"(a) : "l"(p));
    return a;
}
__device__ __forceinline__ float ex2f(float x) {
    float r; asm("ex2.approx.f32 %0, %1;" : "=f"(r) : "f"(x)); return r;
}
__device__ __forceinline__ uint32_t ex2_h2(uint32_t x) {
    uint32_t r; asm("ex2.approx.f16x2 %0, %1;" : "=r"(r) : "r"(x)); return r;
}
__device__ __forceinline__ uint32_t pack_h2(float lo, float hi) {
    uint32_t r; asm("cvt.rn.f16x2.f32 %0, %1, %2;" : "=r"(r) : "f"(hi), "f"(lo)); return r;
}
__device__ __forceinline__ void ldsm4(uint32_t r[4], uint32_t addr) {
    asm volatile("ldmatrix.sync.aligned.m8n8.x4.shared.b16 {%0,%1,%2,%3}, [%4];"
                 : "=r"(r[0]), "=r"(r[1]), "=r"(r[2]), "=r"(r[3]) : "r"(addr));
}
__device__ __forceinline__ void ldsm4t(uint32_t r[4], uint32_t addr) {
    asm volatile("ldmatrix.sync.aligned.m8n8.x4.trans.shared.b16 {%0,%1,%2,%3}, [%4];"
                 : "=r"(r[0]), "=r"(r[1]), "=r"(r[2]), "=r"(r[3]) : "r"(addr));
}
__device__ __forceinline__ void mma16816(float c[4], const uint32_t a[4],
                                         uint32_t b0, uint32_t b1) {
    asm volatile("mma.sync.aligned.m16n8k16.row.col.f32.f16.f16.f32 "
                 "{%0,%1,%2,%3},{%4,%5,%6,%7},{%8,%9},{%0,%1,%2,%3};"
                 : "+f"(c[0]), "+f"(c[1]), "+f"(c[2]), "+f"(c[3])
                 : "r"(a[0]), "r"(a[1]), "r"(a[2]), "r"(a[3]), "r"(b0), "r"(b1));
}
#define CP16(dst, src) \
    asm volatile("cp.async.cg.shared.global [%0], [%1], 16;" :: "r"(dst), "l"(src))
#define CP_COMMIT() asm volatile("cp.async.commit_group;" ::: "memory")
#define CP_WAIT0()  asm volatile("cp.async.wait_group 0;" ::: "memory")
#define CP_WAIT1()  asm volatile("cp.async.wait_group 1;" ::: "memory")

// =====================================================================
// Kernel 1 (merged): (unchanged from R16 — proven)
//   blocks [0,64):    HMMA KV projection, block = (b, mtile64, nquarter96)
//   blocks [64,136):  weight prep -> g_wq (scaled), g_wp
// =====================================================================
__global__ __launch_bounds__(256) void prep_kv_kernel(
    const float* __restrict__ prior,
    const float* __restrict__ g2, const float* __restrict__ b2,
    const float* __restrict__ Wkv,
    const float* __restrict__ Wq, const float* __restrict__ Wp)
{
    int tid = threadIdx.x;

    if (blockIdx.x >= NKV_BLK) {
        int base = (int)(blockIdx.x - NKV_BLK) * 512 + tid;
        #pragma unroll
        for (int it = 0; it < 2; it++) {
            int idx = base + it*256;
            g_wq[idx] = __float2half_rn(Wq[idx] * QSCALE);
            g_wp[idx] = __float2half_rn(Wp[idx]);
        }
        return;
    }

    extern __shared__ char smraw2[];
    const uint32_t SB = smem_u32(smraw2);
    uint32_t* Au = reinterpret_cast<uint32_t*>(smraw2 + O2_A);
    uint32_t* Wu = reinterpret_cast<uint32_t*>(smraw2 + O2_W);

    int kvb = (int)blockIdx.x;
    int b   = kvb >> 4;
    int m0  = ((kvb >> 2) & 3) * 64;
    int nq  = kvb & 3;

    int wid = tid >> 5, lane = tid & 31;
    int gid = lane >> 2, t4 = lane & 3;
    const uint32_t l15 = lane & 15;
    const uint32_t chalf = (lane >> 4) * 16;

    const float2* psrc = reinterpret_cast<const float2*>(
        prior + (size_t)(b*MLEN + m0) * DIMC);
    for (int idx = tid; idx < 64*96; idx += 256) {
        float2 v = psrc[idx];
        Au[(idx / 96)*100 + (idx % 96)] = pack_h2(v.x, v.y);
    }
    for (int idx = tid; idx < 192*48; idx += 256) {
        int r = idx / 48, cp = idx % 48;
        const float2* wsrc = reinterpret_cast<const float2*>(
            Wkv + (size_t)r*384 + nq*96);
        float2 v = wsrc[cp];
        Wu[r*100 + cp] = pack_h2(v.x, v.y);
    }
    __syncthreads();

    {
        int row = tid >> 2, part = tid & 3;
        float s = 0.f, s2 = 0.f;
        uint32_t vals[24];
        #pragma unroll
        for (int j = 0; j < 24; j++) {
            vals[j] = Au[row*100 + part*24 + j];
            float2 f = __half22float2(*reinterpret_cast<__half2*>(&vals[j]));
            s += f.x + f.y;  s2 += f.x*f.x + f.y*f.y;
        }
        s  += __shfl_xor_sync(0xffffffffu, s, 1);
        s  += __shfl_xor_sync(0xffffffffu, s, 2);
        s2 += __shfl_xor_sync(0xffffffffu, s2, 1);
        s2 += __shfl_xor_sync(0xffffffffu, s2, 2);
        float mu   = s * (1.f/DIMC);
        float rstd = rsqrtf(s2*(1.f/DIMC) - mu*mu + 1e-5f);
        #pragma unroll
        for (int j = 0; j < 24; j++) {
            int k = part*48 + 2*j;
            float2 f = __half22float2(*reinterpret_cast<__half2*>(&vals[j]));
            float v0 = (f.x - mu) * rstd * __ldg(g2 + k)     + __ldg(b2 + k);
            float v1 = (f.y - mu) * rstd * __ldg(g2 + k + 1) + __ldg(b2 + k + 1);
            Au[row*100 + part*24 + j] = pack_h2(v0, v1);
        }
    }
    __syncthreads();

    int mw = wid >> 1, nw = wid & 1;
    float acc[6][4];
    #pragma unroll
    for (int j = 0; j < 6; j++)
        #pragma unroll
        for (int q = 0; q < 4; q++) acc[j][q] = 0.f;

    uint32_t xa = SB + O2_A + (mw*16 + l15)*400 + chalf;
    uint32_t wa = SB + O2_W + l15*400 + chalf + nw*96;

    #pragma unroll
    for (int ks = 0; ks < 12; ks++) {
        uint32_t a[4];
        ldsm4(a, xa + ks*32);
        #pragma unroll
        for (int j = 0; j < 3; j++) {
            uint32_t bb[4];
            ldsm4t(bb, wa + ks*16*400 + j*32);
            mma16816(acc[2*j],   a, bb[0], bb[1]);
            mma16816(acc[2*j+1], a, bb[2], bb[3]);
        }
    }

    uint32_t* dst = reinterpret_cast<uint32_t*>((nq < 2) ? g_k : g_v);
    int cbase = (nq & 1) * 48;
    {
        int r = mw*16 + gid;
        size_t row0 = (size_t)(b*MLEN + m0 + r) * 96;
        size_t row8 = row0 + 8*96;
        #pragma unroll
        for (int j = 0; j < 6; j++) {
            int cu = cbase + nw*24 + j*4 + t4;
            dst[row0 + cu] = pack_h2(acc[j][0], acc[j][1]);
            dst[row8 + cu] = pack_h2(acc[j][2], acc[j][3]);
        }
    }
}

// =====================================================================
// Kernel 2: fused pipeline, TILE=64 / 128 threads / 3 CTAs per SM.
// Per-warp structure identical to the proven R16 kernel.
// =====================================================================
__global__ __launch_bounds__(THREADS, 3) void fused_kernel(
    const float* __restrict__ x,
    const float* __restrict__ g1, const float* __restrict__ b1,
    const float* __restrict__ bp, float* __restrict__ out)
{
    extern __shared__ char smraw[];
    const uint32_t SB = smem_u32(smraw);
    uint32_t* XQu = reinterpret_cast<uint32_t*>(smraw + O_XQ);   // stride 100 u32
    float*    bps = reinterpret_cast<float*>(smraw + O_BP);

    int tid  = threadIdx.x;
    int wid  = tid >> 5, lane = tid & 31;
    int gid  = lane >> 2, t4 = lane & 3;
    int b    = blockIdx.x >> 8;                 // 256 tiles per batch
    int n0   = (blockIdx.x & 255) * TILE;
    const size_t xbase = (size_t)b * DIMC * NTOK;

    const uint32_t l15 = lane & 15;
    const uint32_t chalf = (lane >> 4) * 16;
    const uint32_t l7  = lane & 7;
    const uint32_t mrow8 = ((lane >> 4) << 3);
    const uint32_t d8  = ((lane >> 3) & 1) * 16;

    auto stage_w = [&](const __half* W, int chunk) {
        const char* src = (const char*)W + chunk*96*384;
        #pragma unroll
        for (int it = 0; it < 18; it++) {
            int idx = tid + it*THREADS;
            int r = idx / 24, ch = (idx % 24) * 16;
            CP16(SB + O_KV + r*400 + ch, src + r*384 + ch);
        }
        CP_COMMIT();
    };
    auto stage_k = [&](int h) {
        const char* ksrc = (const char*)(g_k + (size_t)b*MLEN*DIMC + h*HD);
        #pragma unroll
        for (int it = 0; it < 8; it++) {
            int idx = tid + it*THREADS;
            int m = idx >> 2, ch = (idx & 3) * 16;
            CP16(SB + O_KV + m*80 + ch, ksrc + m*(DIMC*2) + ch);
        }
        CP_COMMIT();
    };
    auto stage_v = [&](int h) {
        const char* vsrc = (const char*)(g_v + (size_t)b*MLEN*DIMC + h*HD);
        #pragma unroll
        for (int it = 0; it < 8; it++) {
            int idx = tid + it*THREADS;
            int m = idx >> 2, ch = (idx & 3) * 16;
            CP16(SB + O_V + m*80 + ch, vsrc + m*(DIMC*2) + ch);
        }
        CP_COMMIT();
    };

    stage_w(g_wq, 0);    // prefetch Wq chunk 0 under x-load + LN
    for (int i = tid; i < DIMC; i += THREADS) bps[i] = bp[i];

    // ---------- phase 1: load x as fp16 into XQ, LN in place ----------
    for (int idx = tid; idx < TILE*(DIMC/2); idx += THREADS) {
        int cp = idx >> 6, i = idx & 63;
        float v0 = x[xbase + (size_t)(2*cp  )*NTOK + n0 + i];
        float v1 = x[xbase + (size_t)(2*cp+1)*NTOK + n0 + i];
        XQu[i*100 + cp] = pack_h2(v0, v1);
    }
    __syncthreads();
    {
        int row = tid >> 1, hf = tid & 1;   // 64 rows, 2 threads/row
        float s = 0.f, s2 = 0.f;
        uint32_t vals[48];
        #pragma unroll
        for (int j = 0; j < 48; j++) {
            vals[j] = XQu[row*100 + hf*48 + j];
            float2 f = __half22float2(*reinterpret_cast<__half2*>(&vals[j]));
            s += f.x + f.y;  s2 += f.x*f.x + f.y*f.y;
        }
        s  += __shfl_xor_sync(0xffffffffu, s, 1);
        s2 += __shfl_xor_sync(0xffffffffu, s2, 1);
        float mu   = s * (1.f/DIMC);
        float rstd = rsqrtf(s2*(1.f/DIMC) - mu*mu + 1e-5f);
        #pragma unroll
        for (int j = 0; j < 48; j++) {
            int k = hf*96 + 2*j;
            float2 f = __half22float2(*reinterpret_cast<__half2*>(&vals[j]));
            float v0 = (f.x - mu) * rstd * __ldg(g1 + k)     + __ldg(b1 + k);
            float v1 = (f.y - mu) * rstd * __ldg(g1 + k + 1) + __ldg(b1 + k + 1);
            XQu[row*100 + hf*48 + j] = pack_h2(v0, v1);
        }
    }
    CP_WAIT0();
    __syncthreads();   // LN stores + Wq chunk 0 visible

    int mw = wid >> 1, nw = wid & 1;   // 2m x 2n warp grid over 64x192

    // ---------- phase 2: Qproj  Q = X @ Wq(scaled), 2 K-chunks ----------
    {
        float acc[2][12][4];
        #pragma unroll
        for (int mi = 0; mi < 2; mi++)
            #pragma unroll
            for (int j = 0; j < 12; j++)
                #pragma unroll
                for (int q = 0; q < 4; q++) acc[mi][j][q] = 0.f;

        uint32_t xa0 = SB + O_XQ + (mw*32 +      l15)*400 + chalf;
        uint32_t xa1 = SB + O_XQ + (mw*32 + 16 + l15)*400 + chalf;
        uint32_t wa  = SB + O_KV + l15*400 + chalf + nw*192;

        #pragma unroll
        for (int kc = 0; kc < 2; kc++) {
            #pragma unroll
            for (int ks = 0; ks < 6; ks++) {
                uint32_t a0[4], a1[4];
                ldsm4(a0, xa0 + kc*192 + ks*32);
                ldsm4(a1, xa1 + kc*192 + ks*32);
                #pragma unroll
                for (int j = 0; j < 6; j++) {
                    uint32_t bb[4];
                    ldsm4t(bb, wa + ks*16*400 + j*32);
                    mma16816(acc[0][2*j],   a0, bb[0], bb[1]);
                    mma16816(acc[0][2*j+1], a0, bb[2], bb[3]);
                    mma16816(acc[1][2*j],   a1, bb[0], bb[1]);
                    mma16816(acc[1][2*j+1], a1, bb[2], bb[3]);
                }
            }
            __syncthreads();
            if (kc == 0) {
                stage_w(g_wq, 1);
                CP_WAIT0();
                __syncthreads();
            }
        }

        stage_k(0);   // group: K(0)
        stage_v(0);   // group: V(0)

        #pragma unroll
        for (int mi = 0; mi < 2; mi++) {
            int r = mw*32 + mi*16 + gid;
            #pragma unroll
            for (int j = 0; j < 12; j++) {
                int cu = nw*48 + j*4 + t4;
                XQu[r*100 + cu]       = pack_h2(acc[mi][j][0], acc[mi][j][1]);
                XQu[(r + 8)*100 + cu] = pack_h2(acc[mi][j][2], acc[mi][j][3]);
            }
        }
    }

    // ---------- phase 3: attention heads (flash-split, split K/V waits) ----------
    for (int h = 0; h < NH; h++) {
        CP_WAIT1();        // K(h) (oldest group) done; V(h) may be in flight
        __syncthreads();

        uint32_t qa = SB + O_XQ + (wid*16 + l15)*400 + chalf + h*64;
        uint32_t qf[2][4];
        ldsm4(qf[0], qa);
        ldsm4(qf[1], qa + 32);

        float oc[4][4];
        #pragma unroll
        for (int n = 0; n < 4; n++)
            #pragma unroll
            for (int q = 0; q < 4; q++) oc[n][q] = 0.f;
        float mxl = -1e30f, mxh = -1e30f, sl = 0.f, sh = 0.f;

        #pragma unroll
        for (int half = 0; half < 2; half++) {
            float sa[16][4];
            #pragma unroll
            for (int n = 0; n < 16; n++)
                #pragma unroll
                for (int q = 0; q < 4; q++) sa[n][q] = 0.f;

            uint32_t ka = SB + O_KV + (half*128 + l7 + mrow8)*80 + d8;
            #pragma unroll
            for (int ks = 0; ks < 2; ks++) {
                #pragma unroll
                for (int jm = 0; jm < 8; jm++) {
                    uint32_t bb[4];
                    ldsm4(bb, ka + jm*16*80 + ks*32);
                    mma16816(sa[2*jm],   qf[ks], bb[0], bb[1]);
                    mma16816(sa[2*jm+1], qf[ks], bb[2], bb[3]);
                }
            }

            if (half == 1) {
                __syncthreads();   // all K(h) reads done
                if (h + 1 < NH) stage_k(h + 1);
            }

            float cml = -1e30f, cmh = -1e30f;
            #pragma unroll
            for (int n = 0; n < 16; n++) {
                cml = fmaxf(cml, fmaxf(sa[n][0], sa[n][1]));
                cmh = fmaxf(cmh, fmaxf(sa[n][2], sa[n][3]));
            }
            cml = fmaxf(cml, __shfl_xor_sync(0xffffffffu, cml, 1));
            cml = fmaxf(cml, __shfl_xor_sync(0xffffffffu, cml, 2));
            cmh = fmaxf(cmh, __shfl_xor_sync(0xffffffffu, cmh, 1));
            cmh = fmaxf(cmh, __shfl_xor_sync(0xffffffffu, cmh, 2));
            float nml = fmaxf(mxl, cml), nmh = fmaxf(mxh, cmh);
            float fl = ex2f(mxl - nml), fh = ex2f(mxh - nmh);
            mxl = nml; mxh = nmh;

            uint32_t pe[16][2];
            float csl = 0.f, csh = 0.f;
            #pragma unroll
            for (int n = 0; n < 16; n++) {
                pe[n][0] = ex2_h2(pack_h2(sa[n][0] - nml, sa[n][1] - nml));
                pe[n][1] = ex2_h2(pack_h2(sa[n][2] - nmh, sa[n][3] - nmh));
                float2 e0 = __half22float2(*reinterpret_cast<__half2*>(&pe[n][0]));
                float2 e1 = __half22float2(*reinterpret_cast<__half2*>(&pe[n][1]));
                csl += e0.x + e0.y;
                csh += e1.x + e1.y;
            }
            csl += __shfl_xor_sync(0xffffffffu, csl, 1);
            csl += __shfl_xor_sync(0xffffffffu, csl, 2);
            csh += __shfl_xor_sync(0xffffffffu, csh, 1);
            csh += __shfl_xor_sync(0xffffffffu, csh, 2);
            sl = sl*fl + csl;
            sh = sh*fh + csh;
            #pragma unroll
            for (int n = 0; n < 4; n++) {
                oc[n][0] *= fl; oc[n][1] *= fl;
                oc[n][2] *= fh; oc[n][3] *= fh;
            }

            if (half == 0) {
                CP_WAIT0();        // only V(h) pending here
                __syncthreads();
            }

            uint32_t va = SB + O_V + (half*128 + l15)*80 + chalf;
            #pragma unroll
            for (int kt = 0; kt < 8; kt++) {
                uint32_t a[4];
                a[0] = pe[2*kt][0];
                a[1] = pe[2*kt][1];
                a[2] = pe[2*kt+1][0];
                a[3] = pe[2*kt+1][1];
                #pragma unroll
                for (int j = 0; j < 2; j++) {
                    uint32_t bb[4];
                    ldsm4t(bb, va + kt*16*80 + j*32);
                    mma16816(oc[2*j],   a, bb[0], bb[1]);
                    mma16816(oc[2*j+1], a, bb[2], bb[3]);
                }
            }
        }

        float il = 1.f / sl, ih = 1.f / sh;
        int rl = wid*16 + gid;
        #pragma unroll
        for (int n = 0; n < 4; n++) {
            XQu[rl*100     + h*16 + n*4 + t4] = pack_h2(oc[n][0]*il, oc[n][1]*il);
            XQu[(rl+8)*100 + h*16 + n*4 + t4] = pack_h2(oc[n][2]*ih, oc[n][3]*ih);
        }
        __syncthreads();   // V reads done before restage
        if (h + 1 < NH) stage_v(h + 1);
        else            stage_w(g_wp, 0);
    }

    // ---------- phase 4: outproj (2 K-chunks) + direct epilogue ----------
    {
        CP_WAIT0();
        __syncthreads();   // Wp chunk 0 + all O stores visible

        float acc[2][12][4];
        #pragma unroll
        for (int mi = 0; mi < 2; mi++)
            #pragma unroll
            for (int j = 0; j < 12; j++)
                #pragma unroll
                for (int q = 0; q < 4; q++) acc[mi][j][q] = 0.f;

        uint32_t xa0 = SB + O_XQ + (mw*32 +      l15)*400 + chalf;
        uint32_t xa1 = SB + O_XQ + (mw*32 + 16 + l15)*400 + chalf;
        uint32_t wa  = SB + O_KV + l15*400 + chalf + nw*192;

        #pragma unroll
        for (int kc = 0; kc < 2; kc++) {
            #pragma unroll
            for (int ks = 0; ks < 6; ks++) {
                uint32_t a0[4], a1[4];
                ldsm4(a0, xa0 + kc*192 + ks*32);
                ldsm4(a1, xa1 + kc*192 + ks*32);
                #pragma unroll
                for (int j = 0; j < 6; j++) {
                    uint32_t bb[4];
                    ldsm4t(bb, wa + ks*16*400 + j*32);
                    mma16816(acc[0][2*j],   a0, bb[0], bb[1]);
                    mma16816(acc[0][2*j+1], a0, bb[2], bb[3]);
                    mma16816(acc[1][2*j],   a1, bb[0], bb[1]);
                    mma16816(acc[1][2*j+1], a1, bb[2], bb[3]);
                }
            }
            if (kc == 0) {
                __syncthreads();
                stage_w(g_wp, 1);
                CP_WAIT0();
                __syncthreads();
            }
        }

        #pragma unroll
        for (int mi = 0; mi < 2; mi++) {
            int r = mw*32 + mi*16 + gid;
            #pragma unroll
            for (int j = 0; j < 12; j++) {
                int c = nw*96 + j*8 + t4*2;
                size_t g0  = xbase + (size_t)c*NTOK + n0 + r;
                size_t g1a = g0 + NTOK;
                out[g0]      = acc[mi][j][0] + bps[c]     + __ldg(x + g0);
                out[g1a]     = acc[mi][j][1] + bps[c + 1] + __ldg(x + g1a);
                out[g0 + 8]  = acc[mi][j][2] + bps[c]     + __ldg(x + g0 + 8);
                out[g1a + 8] = acc[mi][j][3] + bps[c + 1] + __ldg(x + g1a + 8);
            }
        }
    }
}

// =====================================================================
extern "C" void kernel_launch(void* const* d_in, const int* in_sizes, int n_in,
                              void* d_out, int out_size)
{
    (void)in_sizes; (void)n_in; (void)out_size;
    const float* x     = (const float*)d_in[0];
    const float* prior = (const float*)d_in[1];
    const float* ln1_g = (const float*)d_in[2];
    const float* ln1_b = (const float*)d_in[3];
    const float* ln2_g = (const float*)d_in[4];
    const float* ln2_b = (const float*)d_in[5];
    const float* Wq    = (const float*)d_in[6];
    const float* Wkv   = (const float*)d_in[7];
    const float* Wp    = (const float*)d_in[8];
    const float* bp    = (const float*)d_in[9];
    float* out = (float*)d_out;

    cudaFuncSetAttribute(prep_kv_kernel, cudaFuncAttributeMaxDynamicSharedMemorySize, SMEM2_BYTES);
    cudaFuncSetAttribute(fused_kernel,   cudaFuncAttributeMaxDynamicSharedMemorySize, SMEM_BYTES);

    prep_kv_kernel<<<NKV_BLK + 72, 256, SMEM2_BYTES>>>(prior, ln2_g, ln2_b, Wkv, Wq, Wp);
    fused_kernel<<<BATCH * (NTOK/TILE), THREADS, SMEM_BYTES>>>(x, ln1_g, ln1_b, bp, out);
}